// round 4
// baseline (speedup 1.0000x reference)
#include <cuda_runtime.h>
#include <math_constants.h>

#define BATCH   8
#define G       32
#define NCELLS  (G * G * G)          // 32768
#define NSEG    (2 * BATCH)          // 16 segments (set, batch)
#define MAXPTS  65536                // B*(N+M)
#define LO      (-5.12f)
#define CS      0.32f
#define INV_CS  3.125f
#define HI      (LO + G * CS)
#define BLOCK   256

__device__ unsigned g_count [NSEG * NCELLS];   // per-cell histogram
__device__ uint2    g_cell  [NSEG * NCELLS];   // (start, count) per cell
__device__ unsigned g_cursor[NSEG * NCELLS];   // scatter cursors
__device__ float4   g_pts   [MAXPTS];          // sorted packed (-2x,-2y,-2z,|t|^2)

__device__ __forceinline__ int cell1(float v) {
    int i = (int)floorf((v - LO) * INV_CS);
    return min(max(i, 0), G - 1);
}

// ---------------------------------------------------------------- clear
__global__ void k_clear(float* out) {
    const int i = blockIdx.x * blockDim.x + threadIdx.x;   // 131072 uint4
    ((uint4*)g_count)[i] = make_uint4(0, 0, 0, 0);
    if (i == 0) out[0] = 0.0f;
}

// ---------------------------------------------------------------- count
__global__ void k_count(const float* __restrict__ A, const float* __restrict__ Bp,
                        int N, int M) {
    const int tid = blockIdx.x * blockDim.x + threadIdx.x;
    const int BN = BATCH * N;
    if (tid >= BN + BATCH * M) return;
    int set, b, i;
    const float* src;
    if (tid < BN) { set = 0; b = tid / N; i = tid % N; src = A + (size_t)(b * N + i) * 3; }
    else { set = 1; const int r = tid - BN; b = r / M; i = r % M; src = Bp + (size_t)(b * M + i) * 3; }
    const int cid = (cell1(src[0]) * G + cell1(src[1])) * G + cell1(src[2]);
    atomicAdd(&g_count[(set * BATCH + b) * NCELLS + cid], 1u);
}

// ---------------------------------------------------------------- scan (1 block per segment)
__global__ __launch_bounds__(1024) void k_scan() {
    const int seg = blockIdx.x;
    const int base = seg * NCELLS;
    const int t = threadIdx.x;
    __shared__ unsigned sh[1024];

    const int c0 = t * (NCELLS / 1024);     // 32 cells per thread
    unsigned sum = 0;
    #pragma unroll 8
    for (int k = 0; k < NCELLS / 1024; k++) sum += g_count[base + c0 + k];
    sh[t] = sum;
    __syncthreads();
    // inclusive Hillis-Steele scan over 1024 partials
    for (int off = 1; off < 1024; off <<= 1) {
        unsigned v = (t >= off) ? sh[t - off] : 0u;
        __syncthreads();
        sh[t] += v;
        __syncthreads();
    }
    unsigned run = (t == 0) ? 0u : sh[t - 1];
    #pragma unroll 8
    for (int k = 0; k < NCELLS / 1024; k++) {
        const int c = base + c0 + k;
        const unsigned cnt = g_count[c];
        g_cell[c] = make_uint2(run, cnt);
        g_cursor[c] = run;
        run += cnt;
    }
}

// ---------------------------------------------------------------- scatter
__global__ void k_scatter(const float* __restrict__ A, const float* __restrict__ Bp,
                          int N, int M) {
    const int tid = blockIdx.x * blockDim.x + threadIdx.x;
    const int BN = BATCH * N;
    if (tid >= BN + BATCH * M) return;
    int set, b, i, pbase;
    const float* src;
    if (tid < BN) { set = 0; b = tid / N; i = tid % N;
                    src = A + (size_t)(b * N + i) * 3; pbase = b * N; }
    else { set = 1; const int r = tid - BN; b = r / M; i = r % M;
           src = Bp + (size_t)(b * M + i) * 3; pbase = BN + b * M; }
    const float x = src[0], y = src[1], z = src[2];
    const int cid = (cell1(x) * G + cell1(y)) * G + cell1(z);
    const unsigned pos = atomicAdd(&g_cursor[(set * BATCH + b) * NCELLS + cid], 1u);
    g_pts[pbase + pos] = make_float4(-2.f * x, -2.f * y, -2.f * z,
                                     x * x + y * y + z * z);
}

// ---------------------------------------------------------------- query
__global__ __launch_bounds__(BLOCK) void k_query(int N, int M,
                                                 float inv1, float inv2,
                                                 float* __restrict__ out) {
    const int tid = blockIdx.x * blockDim.x + threadIdx.x;
    const int BN = BATCH * N;
    const int total = BN + BATCH * M;

    float contrib = 0.0f;
    if (tid < total) {
        int side, b, qoff, qbase, refbase;
        if (tid < BN) { side = 0; b = tid / N; qoff = tid % N;
                        qbase = b * N; refbase = BN + b * M; }
        else { side = 1; const int r = tid - BN; b = r / M; qoff = r % M;
               qbase = BN + b * M; refbase = b * N; }
        const int refseg = ((side ^ 1) * BATCH + b) * NCELLS;

        const float4 q4 = g_pts[qbase + qoff];
        const float qx = -0.5f * q4.x, qy = -0.5f * q4.y, qz = -0.5f * q4.z;
        const float qw = q4.w;
        const bool prune = (qx >= LO && qx < HI && qy >= LO && qy < HI &&
                            qz >= LO && qz < HI);
        const int cx = cell1(qx), cy = cell1(qy), cz = cell1(qz);

        float best = CUDART_INF_F;     // best partial = |t|^2 - 2 t.q

        for (int s = 0; s < G; s++) {
            if (s >= 1 && prune) {
                const float r = (float)(s - 1) * CS;
                if (r * r - qw > best) break;
            }
            const int x0 = max(cx - s, 0), x1 = min(cx + s, G - 1);
            const int y0 = max(cy - s, 0), y1 = min(cy + s, G - 1);
            const int z0 = max(cz - s, 0), z1 = min(cz + s, G - 1);
            for (int xi = x0; xi <= x1; xi++) {
                const bool xe = (xi == cx - s) || (xi == cx + s);
                for (int yi = y0; yi <= y1; yi++) {
                    const bool face = xe || (yi == cy - s) || (yi == cy + s);
                    const int rowc = refseg + (xi * G + yi) * G;
                    int zlist[2];
                    int nz;
                    int zfrom = z0, zto = z1;
                    if (face) { nz = -1; }
                    else {
                        nz = 0;
                        if (cz - s >= 0)     zlist[nz++] = cz - s;
                        if (cz + s <= G - 1) zlist[nz++] = cz + s;
                    }
                    for (int zz = 0; ; zz++) {
                        int zi;
                        if (nz < 0) { zi = zfrom + zz; if (zi > zto) break; }
                        else { if (zz >= nz) break; zi = zlist[zz]; }
                        const uint2 sc = __ldg(&g_cell[rowc + zi]);
                        const float4* tp = &g_pts[refbase + sc.x];
                        for (unsigned j = 0; j < sc.y; j++) {
                            const float4 t4 = __ldg(&tp[j]);
                            const float p = fmaf(t4.z, qz,
                                            fmaf(t4.y, qy,
                                            fmaf(t4.x, qx, t4.w)));
                            best = fminf(best, p);
                        }
                    }
                }
            }
        }
        contrib = fmaxf(qw + best, 0.0f) * (side ? inv2 : inv1);
    }

    // block reduction
    #pragma unroll
    for (int o = 16; o > 0; o >>= 1)
        contrib += __shfl_down_sync(0xffffffffu, contrib, o);
    __shared__ float wsum[BLOCK / 32];
    if ((threadIdx.x & 31) == 0) wsum[threadIdx.x >> 5] = contrib;
    __syncthreads();
    if (threadIdx.x < BLOCK / 32) {
        float v = wsum[threadIdx.x];
        #pragma unroll
        for (int o = BLOCK / 64; o > 0; o >>= 1)
            v += __shfl_down_sync(0xffu, v, o);
        if (threadIdx.x == 0) atomicAdd(out, v);
    }
}

// ---------------------------------------------------------------- launch
extern "C" void kernel_launch(void* const* d_in, const int* in_sizes, int n_in,
                              void* d_out, int out_size)
{
    const float* input  = (const float*)d_in[0];   // [B, N, 3]
    const float* target = (const float*)d_in[1];   // [B, M, 3]
    float* out = (float*)d_out;

    const int B = BATCH, D = 3;
    const int N = in_sizes[0] / (B * D);
    const int M = in_sizes[1] / (B * D);
    const int total = B * (N + M);

    k_clear<<<(NSEG * NCELLS / 4 + BLOCK - 1) / BLOCK, BLOCK>>>(out);
    k_count<<<(total + BLOCK - 1) / BLOCK, BLOCK>>>(input, target, N, M);
    k_scan<<<NSEG, 1024>>>();
    k_scatter<<<(total + BLOCK - 1) / BLOCK, BLOCK>>>(input, target, N, M);
    k_query<<<(total + BLOCK - 1) / BLOCK, BLOCK>>>(
        N, M, 1.0f / ((float)B * (float)N), 1.0f / ((float)B * (float)M), out);
}